// round 16
// baseline (speedup 1.0000x reference)
#include <cuda_runtime.h>
#include <cuda_bf16.h>
#include <cstdint>

// ChannelBlockImportanceGate: forward value == hard top-k block mask.
// features [8,256,132,132] f32, enabled int32. BLOCK=8 -> 17x17=289 blocks,
// keep = 72. Ties: lower flat index wins (lax.top_k).
//
// R16: R15 (best known, 51.97us) + L2 evict-first cache hint on the READ
// stream (cp.async.cg.L2::cache_hint with createpolicy evict_first) --
// symmetric completion of R15's store-side hint. Both streams are
// zero-reuse; keeping dead lines out of L2 reduces LTS churn.
// All arithmetic byte-identical to R15.

#define HH   132
#define WW   132
#define NBX  17
#define NBLK 289
#define KEEP 72
#define NPIX (HH*WW)
#define NTHREADS 256
#define CHUNK_ROWS 16
#define NCHUNK 9
#define ROW_F4 33           // 132 floats = 33 float4 per row

__device__ __forceinline__ uint64_t l2_evict_first_policy() {
    uint64_t pol;
    asm volatile("createpolicy.fractional.L2::evict_first.b64 %0, 1.0;\n"
                 : "=l"(pol));
    return pol;
}

__device__ __forceinline__ void cp_async16_ef(void* smem_ptr, const void* gptr,
                                              uint64_t pol) {
    uint32_t s = (uint32_t)__cvta_generic_to_shared(smem_ptr);
    asm volatile("cp.async.cg.shared.global.L2::cache_hint [%0], [%1], 16, %2;\n"
                 :: "r"(s), "l"(gptr), "l"(pol));
}
#define CP_COMMIT() asm volatile("cp.async.commit_group;\n" ::: "memory")
#define CP_WAIT1()  asm volatile("cp.async.wait_group 1;\n" ::: "memory")
#define CP_WAIT0()  asm volatile("cp.async.wait_group 0;\n" ::: "memory")

__global__ __launch_bounds__(NTHREADS)
void gate_kernel(const float* __restrict__ in,
                 const int*  __restrict__ enabled,
                 float* __restrict__ out)
{
    const int bc = blockIdx.x;
    const long long base = (long long)bc * NPIX;
    const int tid  = threadIdx.x;
    const int warp = tid >> 5;
    const int lane = tid & 31;

    if (*enabled == 0) {
        float4 ones = make_float4(1.f, 1.f, 1.f, 1.f);
        float4* o4 = (float4*)(out + base);
        for (int p = tid; p < NPIX / 4; p += NTHREADS) __stcs(o4 + p, ones);
        return;
    }

    __shared__ float4 buf[2][CHUNK_ROWS * ROW_F4];   // 16.9 KB staging
    __shared__ float  rbsl[CHUNK_ROWS * NBX];        // chunk-local partials
    __shared__ float  pooled[NBLK];
    __shared__ float  hardm[NBLK];
    __shared__ int    hist[32];
    __shared__ float  wmin[8], wmax[8];
    __shared__ float  s_minv, s_scale;
    __shared__ int    s_bb, s_chi, s_mcnt;
    __shared__ int    bblist[NBLK];

    if (tid < 32) hist[tid] = 0;
    if (tid == 0) s_mcnt = 0;

    const float4* src4 = (const float4*)(in + base);
    const uint64_t pol = l2_evict_first_policy();

    // ---- Phase A+B fused: double-buffered cp.async; per-chunk pooled fold.
    {
        int n4 = CHUNK_ROWS * ROW_F4;
        for (int i = tid; i < n4; i += NTHREADS)
            cp_async16_ef(&buf[0][i], src4 + i, pol);
        CP_COMMIT();
    }
    for (int c = 0; c < NCHUNK; c++) {
        int r0 = c * CHUNK_ROWS;
        int nr = min(CHUNK_ROWS, HH - r0);
        if (c + 1 < NCHUNK) {
            int r0n = (c + 1) * CHUNK_ROWS;
            int nrn = min(CHUNK_ROWS, HH - r0n);
            int n4  = nrn * ROW_F4;
            const float4* g = src4 + r0n * ROW_F4;
            float4* b = buf[(c + 1) & 1];
            for (int i = tid; i < n4; i += NTHREADS)
                cp_async16_ef(&b[i], g + i, pol);
            CP_COMMIT();
            CP_WAIT1();
        } else {
            CP_WAIT0();
        }
        __syncthreads();          // staged data visible; prior fold done

        // consume chunk c: per-(local row, bx) partial, canonical tree
        const float* bf = (const float*)buf[c & 1];
        int tasks = nr * NBX;
        for (int t = tid; t < tasks; t += NTHREADS) {
            int rl = t / NBX;
            int bx = t - rl * NBX;
            const float* row = bf + rl * WW;
            float4 a = *(const float4*)(row + bx * 8);
            float4 b4;
            if (bx < 16) b4 = *(const float4*)(row + bx * 8 + 4);
            else         b4 = make_float4(0.f, 0.f, 0.f, 0.f);
            rbsl[rl * NBX + bx] =
                  ((fabsf(a.x) + fabsf(b4.x)) + (fabsf(a.z) + fabsf(b4.z)))
                + ((fabsf(a.y) + fabsf(b4.y)) + (fabsf(a.w) + fabsf(b4.w)));
        }
        __syncthreads();          // rbsl complete for chunk c

        // pooled fold: chunk c holds block-rows 2c (rows 0..7) and 2c+1
        // (rows 8..15); tail chunk 8 holds block-row 16 (4 valid rows).
        // Increasing-row order -> bitwise identical to all passing rounds.
        int nb = (c == NCHUNK - 1) ? NBX : 2 * NBX;
        if (tid < nb) {
            int lr = tid / NBX;
            int bx = tid - lr * NBX;
            int nr2 = (c == NCHUNK - 1) ? 4 : 8;
            float s = 0.0f;
            #pragma unroll
            for (int r = 0; r < 8; r++)
                if (r < nr2) s += rbsl[(lr * 8 + r) * NBX + bx];
            pooled[c * 34 + tid] = s;
        }
        // fold protected by the next iteration's first barrier
    }
    __syncthreads();              // last fold visible

    // ---- min/max over pooled
    float lmin = 3.4e38f, lmax = -3.4e38f;
    for (int b = tid; b < NBLK; b += NTHREADS) {
        float s = pooled[b];
        lmin = fminf(lmin, s);
        lmax = fmaxf(lmax, s);
    }
    #pragma unroll
    for (int off = 16; off > 0; off >>= 1) {
        lmin = fminf(lmin, __shfl_down_sync(0xffffffffu, lmin, off));
        lmax = fmaxf(lmax, __shfl_down_sync(0xffffffffu, lmax, off));
    }
    if (lane == 0) { wmin[warp] = lmin; wmax[warp] = lmax; }
    __syncthreads();

    // ---- warp 0: global min/max -> bin scale
    if (warp == 0) {
        float mn = (lane < 8) ? wmin[lane] : 3.4e38f;
        float mx = (lane < 8) ? wmax[lane] : -3.4e38f;
        #pragma unroll
        for (int off = 4; off > 0; off >>= 1) {
            mn = fminf(mn, __shfl_down_sync(0xffffffffu, mn, off));
            mx = fmaxf(mx, __shfl_down_sync(0xffffffffu, mx, off));
        }
        if (lane == 0) {
            float r = mx - mn;
            s_minv  = mn;
            s_scale = (r > 0.0f) ? (32.0f / r) : 0.0f;
        }
    }
    __syncthreads();

    // ---- histogram
    {
        float minv = s_minv, scale = s_scale;
        for (int b = tid; b < NBLK; b += NTHREADS) {
            int bin = min((int)((pooled[b] - minv) * scale), 31);
            atomicAdd(&hist[bin], 1);
        }
    }
    __syncthreads();

    // ---- warp 0: suffix scan -> boundary bin bb, count strictly above (chi)
    if (warp == 0) {
        int cge = hist[lane];
        #pragma unroll
        for (int off = 1; off < 32; off <<= 1) {
            int t = __shfl_down_sync(0xffffffffu, cge, off);
            if (lane + off < 32) cge += t;
        }
        int cgt = __shfl_down_sync(0xffffffffu, cge, 1);
        if (lane == 31) cgt = 0;
        if (cgt < KEEP && cge >= KEEP) { s_bb = lane; s_chi = cgt; }
    }
    __syncthreads();

    // ---- classify; collect boundary-bin items
    {
        float minv = s_minv, scale = s_scale;
        int bb = s_bb;
        for (int b = tid; b < NBLK; b += NTHREADS) {
            int bin = min((int)((pooled[b] - minv) * scale), 31);
            if (bin > bb)      hardm[b] = 1.0f;
            else if (bin < bb) hardm[b] = 0.0f;
            else               bblist[atomicAdd(&s_mcnt, 1)] = b;
        }
    }
    __syncthreads();

    // ---- exact rank inside boundary bin (tie: lower index wins)
    {
        int m = s_mcnt;
        int budget = KEEP - s_chi;
        for (int it = tid; it < m; it += NTHREADS) {
            int i = bblist[it];
            float vi = pooled[i];
            int c = 0;
            for (int j = 0; j < m; j++) {
                int jj = bblist[j];
                float vj = pooled[jj];
                c += (vj > vi) || (vj == vi && jj < i);
            }
            hardm[i] = (c < budget) ? 1.0f : 0.0f;
        }
    }
    __syncthreads();

    // ---- Phase D: expand to pixels; evict-first streaming float4 stores
    for (int by = warp; by < NBX; by += 8) {
        float  mv  = hardm[by * NBX + (lane >> 1)];
        float  m16 = hardm[by * NBX + 16];
        float4 v4  = make_float4(mv, mv, mv, mv);
        float4 v16 = make_float4(m16, m16, m16, m16);
        int ylim = min(HH - by * 8, 8);
        float* obase = out + base + (by * 8) * WW;
        for (int r = 0; r < ylim; r++) {
            float* orow = obase + r * WW;
            __stcs((float4*)(orow + lane * 4), v4);
            if (lane == 0) __stcs((float4*)(orow + 128), v16);
        }
    }
}

extern "C" void kernel_launch(void* const* d_in, const int* in_sizes, int n_in,
                              void* d_out, int out_size)
{
    const float* features = (const float*)d_in[0];
    const int*   enabled  = (const int*)d_in[1];
    float* out = (float*)d_out;

    const int n_channels = out_size / NPIX;   // 2048
    gate_kernel<<<n_channels, NTHREADS>>>(features, enabled, out);
}

// round 17
// speedup vs baseline: 1.0012x; 1.0012x over previous
#include <cuda_runtime.h>
#include <cuda_bf16.h>
#include <cstdint>

// ChannelBlockImportanceGate: forward value == hard top-k block mask
// (straight-through soft term cancels to within 1 ulp of the hard mask).
// features [8,256,132,132] f32, enabled int32. BLOCK=8 -> 17x17=289 blocks,
// keep = 72. Ties: lower flat index wins (lax.top_k).
//
// FINAL (== R15, best measured 51.97us / ncu 46.24us / rel_err 0.0):
//  - fused load+pool: double-buffered cp.async staging, per-chunk pooled
//    fold (bitwise-identical FP reduction tree throughout the session)
//  - exact top-72 via 32-bin histogram select + pairwise rank of the
//    boundary bin only (reproduces lax.top_k tie semantics exactly)
//  - evict-first streaming stores (__stcs) -- the one L2 lever that moved
//    the ceiling (R15: +0.1us bench, ncu 47.6->46.2)
// Effective traffic 293.6MB / 46.2us ~= 6.35 TB/s: at the practical mixed
// R/W HBM ceiling for this part; all structural levers verified neutral.

#define HH   132
#define WW   132
#define NBX  17
#define NBLK 289
#define KEEP 72
#define NPIX (HH*WW)
#define NTHREADS 256
#define CHUNK_ROWS 16
#define NCHUNK 9
#define ROW_F4 33           // 132 floats = 33 float4 per row

__device__ __forceinline__ void cp_async16(void* smem_ptr, const void* gptr) {
    uint32_t s = (uint32_t)__cvta_generic_to_shared(smem_ptr);
    asm volatile("cp.async.cg.shared.global [%0], [%1], 16;\n"
                 :: "r"(s), "l"(gptr));
}
#define CP_COMMIT() asm volatile("cp.async.commit_group;\n" ::: "memory")
#define CP_WAIT1()  asm volatile("cp.async.wait_group 1;\n" ::: "memory")
#define CP_WAIT0()  asm volatile("cp.async.wait_group 0;\n" ::: "memory")

__global__ __launch_bounds__(NTHREADS)
void gate_kernel(const float* __restrict__ in,
                 const int*  __restrict__ enabled,
                 float* __restrict__ out)
{
    const int bc = blockIdx.x;
    const long long base = (long long)bc * NPIX;
    const int tid  = threadIdx.x;
    const int warp = tid >> 5;
    const int lane = tid & 31;

    if (*enabled == 0) {
        float4 ones = make_float4(1.f, 1.f, 1.f, 1.f);
        float4* o4 = (float4*)(out + base);
        for (int p = tid; p < NPIX / 4; p += NTHREADS) __stcs(o4 + p, ones);
        return;
    }

    __shared__ float4 buf[2][CHUNK_ROWS * ROW_F4];   // 16.9 KB staging
    __shared__ float  rbsl[CHUNK_ROWS * NBX];        // chunk-local partials
    __shared__ float  pooled[NBLK];
    __shared__ float  hardm[NBLK];
    __shared__ int    hist[32];
    __shared__ float  wmin[8], wmax[8];
    __shared__ float  s_minv, s_scale;
    __shared__ int    s_bb, s_chi, s_mcnt;
    __shared__ int    bblist[NBLK];

    if (tid < 32) hist[tid] = 0;
    if (tid == 0) s_mcnt = 0;

    const float4* src4 = (const float4*)(in + base);

    // ---- Phase A+B fused: double-buffered cp.async; per-chunk pooled fold.
    {
        int n4 = CHUNK_ROWS * ROW_F4;
        for (int i = tid; i < n4; i += NTHREADS)
            cp_async16(&buf[0][i], src4 + i);
        CP_COMMIT();
    }
    for (int c = 0; c < NCHUNK; c++) {
        int r0 = c * CHUNK_ROWS;
        int nr = min(CHUNK_ROWS, HH - r0);
        if (c + 1 < NCHUNK) {
            int r0n = (c + 1) * CHUNK_ROWS;
            int nrn = min(CHUNK_ROWS, HH - r0n);
            int n4  = nrn * ROW_F4;
            const float4* g = src4 + r0n * ROW_F4;
            float4* b = buf[(c + 1) & 1];
            for (int i = tid; i < n4; i += NTHREADS)
                cp_async16(&b[i], g + i);
            CP_COMMIT();
            CP_WAIT1();
        } else {
            CP_WAIT0();
        }
        __syncthreads();          // staged data visible; prior fold done

        // consume chunk c: per-(local row, bx) partial, canonical tree
        const float* bf = (const float*)buf[c & 1];
        int tasks = nr * NBX;
        for (int t = tid; t < tasks; t += NTHREADS) {
            int rl = t / NBX;
            int bx = t - rl * NBX;
            const float* row = bf + rl * WW;
            float4 a = *(const float4*)(row + bx * 8);
            float4 b4;
            if (bx < 16) b4 = *(const float4*)(row + bx * 8 + 4);
            else         b4 = make_float4(0.f, 0.f, 0.f, 0.f);
            rbsl[rl * NBX + bx] =
                  ((fabsf(a.x) + fabsf(b4.x)) + (fabsf(a.z) + fabsf(b4.z)))
                + ((fabsf(a.y) + fabsf(b4.y)) + (fabsf(a.w) + fabsf(b4.w)));
        }
        __syncthreads();          // rbsl complete for chunk c

        // pooled fold: chunk c holds block-rows 2c (rows 0..7) and 2c+1
        // (rows 8..15); tail chunk 8 holds block-row 16 (4 valid rows).
        // Increasing-row order -> bitwise identical to all passing rounds.
        int nb = (c == NCHUNK - 1) ? NBX : 2 * NBX;
        if (tid < nb) {
            int lr = tid / NBX;
            int bx = tid - lr * NBX;
            int nr2 = (c == NCHUNK - 1) ? 4 : 8;
            float s = 0.0f;
            #pragma unroll
            for (int r = 0; r < 8; r++)
                if (r < nr2) s += rbsl[(lr * 8 + r) * NBX + bx];
            pooled[c * 34 + tid] = s;
        }
        // fold protected by the next iteration's first barrier
    }
    __syncthreads();              // last fold visible

    // ---- min/max over pooled
    float lmin = 3.4e38f, lmax = -3.4e38f;
    for (int b = tid; b < NBLK; b += NTHREADS) {
        float s = pooled[b];
        lmin = fminf(lmin, s);
        lmax = fmaxf(lmax, s);
    }
    #pragma unroll
    for (int off = 16; off > 0; off >>= 1) {
        lmin = fminf(lmin, __shfl_down_sync(0xffffffffu, lmin, off));
        lmax = fmaxf(lmax, __shfl_down_sync(0xffffffffu, lmax, off));
    }
    if (lane == 0) { wmin[warp] = lmin; wmax[warp] = lmax; }
    __syncthreads();

    // ---- warp 0: global min/max -> bin scale
    if (warp == 0) {
        float mn = (lane < 8) ? wmin[lane] : 3.4e38f;
        float mx = (lane < 8) ? wmax[lane] : -3.4e38f;
        #pragma unroll
        for (int off = 4; off > 0; off >>= 1) {
            mn = fminf(mn, __shfl_down_sync(0xffffffffu, mn, off));
            mx = fmaxf(mx, __shfl_down_sync(0xffffffffu, mx, off));
        }
        if (lane == 0) {
            float r = mx - mn;
            s_minv  = mn;
            s_scale = (r > 0.0f) ? (32.0f / r) : 0.0f;
        }
    }
    __syncthreads();

    // ---- histogram
    {
        float minv = s_minv, scale = s_scale;
        for (int b = tid; b < NBLK; b += NTHREADS) {
            int bin = min((int)((pooled[b] - minv) * scale), 31);
            atomicAdd(&hist[bin], 1);
        }
    }
    __syncthreads();

    // ---- warp 0: suffix scan -> boundary bin bb, count strictly above (chi)
    if (warp == 0) {
        int cge = hist[lane];
        #pragma unroll
        for (int off = 1; off < 32; off <<= 1) {
            int t = __shfl_down_sync(0xffffffffu, cge, off);
            if (lane + off < 32) cge += t;
        }
        int cgt = __shfl_down_sync(0xffffffffu, cge, 1);
        if (lane == 31) cgt = 0;
        if (cgt < KEEP && cge >= KEEP) { s_bb = lane; s_chi = cgt; }
    }
    __syncthreads();

    // ---- classify; collect boundary-bin items
    {
        float minv = s_minv, scale = s_scale;
        int bb = s_bb;
        for (int b = tid; b < NBLK; b += NTHREADS) {
            int bin = min((int)((pooled[b] - minv) * scale), 31);
            if (bin > bb)      hardm[b] = 1.0f;
            else if (bin < bb) hardm[b] = 0.0f;
            else               bblist[atomicAdd(&s_mcnt, 1)] = b;
        }
    }
    __syncthreads();

    // ---- exact rank inside boundary bin (tie: lower index wins)
    {
        int m = s_mcnt;
        int budget = KEEP - s_chi;
        for (int it = tid; it < m; it += NTHREADS) {
            int i = bblist[it];
            float vi = pooled[i];
            int c = 0;
            for (int j = 0; j < m; j++) {
                int jj = bblist[j];
                float vj = pooled[jj];
                c += (vj > vi) || (vj == vi && jj < i);
            }
            hardm[i] = (c < budget) ? 1.0f : 0.0f;
        }
    }
    __syncthreads();

    // ---- Phase D: expand to pixels; evict-first streaming float4 stores
    for (int by = warp; by < NBX; by += 8) {
        float  mv  = hardm[by * NBX + (lane >> 1)];
        float  m16 = hardm[by * NBX + 16];
        float4 v4  = make_float4(mv, mv, mv, mv);
        float4 v16 = make_float4(m16, m16, m16, m16);
        int ylim = min(HH - by * 8, 8);
        float* obase = out + base + (by * 8) * WW;
        for (int r = 0; r < ylim; r++) {
            float* orow = obase + r * WW;
            __stcs((float4*)(orow + lane * 4), v4);
            if (lane == 0) __stcs((float4*)(orow + 128), v16);
        }
    }
}

extern "C" void kernel_launch(void* const* d_in, const int* in_sizes, int n_in,
                              void* d_out, int out_size)
{
    const float* features = (const float*)d_in[0];
    const int*   enabled  = (const int*)d_in[1];
    float* out = (float*)d_out;

    const int n_channels = out_size / NPIX;   // 2048
    gate_kernel<<<n_channels, NTHREADS>>>(features, enabled, out);
}